// round 2
// baseline (speedup 1.0000x reference)
#include <cuda_runtime.h>
#include <math.h>

#define NNODES 50000
#define NEDGES 400000
#define HEADS  4

// ---------------- scratch (device globals; no allocation allowed) -------------
__device__ float g_Wx  [NNODES * 512];   // Wx for current layer (max dout=512)
__device__ float g_bufA[NNODES * 256];   // layer-1 output / layer-2 input
__device__ float g_bufB[NNODES * 256];   // layer-2 output / layer-3 input
__device__ float g_ssrc[NNODES * HEADS];
__device__ float g_sdst[NNODES * HEADS];
__device__ float g_denom[NNODES * HEADS];
__device__ float g_eexp[NEDGES * HEADS];

// ---------------- SGEMM: C[M,N] = A[M,K] @ B[K,N] ----------------------------
// 128x128 block tile, BK=8, 256 threads, 8x8 micro-tile per thread.
// N is always a multiple of 128 here (256 or 512). M, K arbitrary.
#define BM 128
#define BN 128
#define BK 8
#define TM 8
#define TN 8

__global__ __launch_bounds__(256, 2)
void sgemm_kernel(const float* __restrict__ A, const float* __restrict__ B,
                  float* __restrict__ C, int M, int N, int K)
{
    __shared__ float As[BK][BM];
    __shared__ float Bs[BK][BN];

    const int tid = threadIdx.x;
    const int block_row = blockIdx.y * BM;
    const int block_col = blockIdx.x * BN;

    const int tx = tid % 16;           // 0..15 -> col group
    const int ty = tid / 16;           // 0..15 -> row group

    // A-tile load mapping: 128 rows x 8 cols = 1024 floats, 4 per thread
    const int a_row = tid >> 1;        // 0..127
    const int a_col = (tid & 1) * 4;   // 0 or 4
    // B-tile load mapping: 8 rows x 128 cols, float4 per thread
    const int b_row = tid >> 5;        // 0..7
    const int b_col = (tid & 31) * 4;  // 0..124

    float acc[TM][TN];
#pragma unroll
    for (int i = 0; i < TM; i++)
#pragma unroll
        for (int j = 0; j < TN; j++) acc[i][j] = 0.0f;

    for (int k0 = 0; k0 < K; k0 += BK) {
        // load A tile (transposed into As[k][m]) with bounds checks
        const int gr = block_row + a_row;
#pragma unroll
        for (int i = 0; i < 4; i++) {
            const int gc = k0 + a_col + i;
            float v = 0.0f;
            if (gr < M && gc < K) v = A[(long long)gr * K + gc];
            As[a_col + i][a_row] = v;
        }
        // load B tile (gc always < N since N % 128 == 0)
        {
            const int gk = k0 + b_row;
            float4 v = make_float4(0.f, 0.f, 0.f, 0.f);
            if (gk < K)
                v = *(const float4*)&B[(long long)gk * N + block_col + b_col];
            Bs[b_row][b_col + 0] = v.x;
            Bs[b_row][b_col + 1] = v.y;
            Bs[b_row][b_col + 2] = v.z;
            Bs[b_row][b_col + 3] = v.w;
        }
        __syncthreads();

#pragma unroll
        for (int k = 0; k < BK; k++) {
            float ar[TM], br[TN];
            // vectorized shared loads (32B-aligned)
            *(float4*)&ar[0] = *(const float4*)&As[k][ty * TM + 0];
            *(float4*)&ar[4] = *(const float4*)&As[k][ty * TM + 4];
            *(float4*)&br[0] = *(const float4*)&Bs[k][tx * TN + 0];
            *(float4*)&br[4] = *(const float4*)&Bs[k][tx * TN + 4];
#pragma unroll
            for (int i = 0; i < TM; i++)
#pragma unroll
                for (int j = 0; j < TN; j++)
                    acc[i][j] = fmaf(ar[i], br[j], acc[i][j]);
        }
        __syncthreads();
    }

    // store
#pragma unroll
    for (int i = 0; i < TM; i++) {
        const int gr = block_row + ty * TM + i;
        if (gr < M) {
            float* c = &C[(long long)gr * N + block_col + tx * TN];
            *(float4*)&c[0] = make_float4(acc[i][0], acc[i][1], acc[i][2], acc[i][3]);
            *(float4*)&c[4] = make_float4(acc[i][4], acc[i][5], acc[i][6], acc[i][7]);
        }
    }
}

// ---------------- per-(node,head) attention scores ----------------------------
// s_src[n,h] = dot(Wx[n,h,:], a[:hd]);  s_dst[n,h] = dot(Wx[n,h,:], a[hd:])
__global__ void scores_kernel(const float* __restrict__ Wx,
                              const float* __restrict__ a,
                              float* __restrict__ s_src, float* __restrict__ s_dst,
                              int n, int hd)
{
    const int warp = (blockIdx.x * blockDim.x + threadIdx.x) >> 5;
    const int lane = threadIdx.x & 31;
    if (warp >= n * HEADS) return;
    const int node = warp / HEADS;
    const int h    = warp % HEADS;
    const float* row = Wx + (long long)node * HEADS * hd + h * hd;
    float ss = 0.f, sd = 0.f;
    for (int d = lane; d < hd; d += 32) {
        const float v = row[d];
        ss = fmaf(v, a[d], ss);
        sd = fmaf(v, a[hd + d], sd);
    }
#pragma unroll
    for (int o = 16; o; o >>= 1) {
        ss += __shfl_xor_sync(0xffffffffu, ss, o);
        sd += __shfl_xor_sync(0xffffffffu, sd, o);
    }
    if (lane == 0) {
        s_src[node * HEADS + h] = ss;
        s_dst[node * HEADS + h] = sd;
    }
}

// ---------------- per-edge attention logits + softmax denominator -------------
__global__ void edge_attn_kernel(const int* __restrict__ src,
                                 const int* __restrict__ dst,
                                 const float* __restrict__ s_src,
                                 const float* __restrict__ s_dst,
                                 float* __restrict__ eexp,
                                 float* __restrict__ denom, int E)
{
    const int e = blockIdx.x * blockDim.x + threadIdx.x;
    if (e >= E) return;
    const int s = src[e];
    const int d = dst[e];
#pragma unroll
    for (int h = 0; h < HEADS; h++) {
        float v = s_src[s * HEADS + h] + s_dst[d * HEADS + h];
        v = (v > 0.f) ? v : 0.2f * v;          // LeakyReLU(0.2)
        const float ex = expf(v);
        eexp[e * HEADS + h] = ex;
        atomicAdd(&denom[d * HEADS + h], ex);
    }
}

// ---------------- weighted scatter-add aggregation ----------------------------
// out[dst] += alpha * Wx[src], HD = head dim (dout = 4*HD). One float4 per thread.
template <int HD>
__global__ void aggregate_kernel(const int* __restrict__ src,
                                 const int* __restrict__ dst,
                                 const float* __restrict__ eexp,
                                 const float* __restrict__ denom,
                                 const float* __restrict__ Wx,
                                 float* __restrict__ out, int E)
{
    const long long gidx = (long long)blockIdx.x * blockDim.x + threadIdx.x;
    const int e = (int)(gidx / HD);   // HD threads per edge (each covers 4 cols)
    const int t = (int)(gidx % HD);
    if (e >= E) return;
    const int s = src[e];
    const int d = dst[e];
    const int col = t * 4;            // 0 .. 4*HD-4
    const int h = col / HD;           // head index (4-float group never crosses heads)
    const float alpha = eexp[e * HEADS + h] / (denom[d * HEADS + h] + 1e-8f);
    const float4 w = *(const float4*)&Wx[(long long)s * (4 * HD) + col];
    float* o = &out[(long long)d * (4 * HD) + col];
    atomicAdd(o + 0, alpha * w.x);
    atomicAdd(o + 1, alpha * w.y);
    atomicAdd(o + 2, alpha * w.z);
    atomicAdd(o + 3, alpha * w.w);
}

// ---------------- ELU + LayerNorm (in-place), one warp per node ----------------
template <int DOUT>
__global__ void epilogue_kernel(float* __restrict__ x,
                                const float* __restrict__ g,
                                const float* __restrict__ b, int n)
{
    const int warp = (blockIdx.x * blockDim.x + threadIdx.x) >> 5;
    const int lane = threadIdx.x & 31;
    if (warp >= n) return;
    float* row = x + (long long)warp * DOUT;
    constexpr int PER = DOUT / 32;
    float vals[PER];
    float sum = 0.f, sumsq = 0.f;
#pragma unroll
    for (int i = 0; i < PER; i++) {
        float v = row[lane + i * 32];
        v = (v > 0.f) ? v : (expf(v) - 1.0f);   // ELU(alpha=1)
        vals[i] = v;
        sum += v;
        sumsq = fmaf(v, v, sumsq);
    }
#pragma unroll
    for (int o = 16; o; o >>= 1) {
        sum   += __shfl_xor_sync(0xffffffffu, sum, o);
        sumsq += __shfl_xor_sync(0xffffffffu, sumsq, o);
    }
    const float inv = 1.0f / (float)DOUT;
    const float mu  = sum * inv;
    const float var = sumsq * inv - mu * mu;
    const float rs  = rsqrtf(var + 1e-5f);
#pragma unroll
    for (int i = 0; i < PER; i++) {
        const int c = lane + i * 32;
        row[c] = (vals[i] - mu) * rs * g[c] + b[c];
    }
}

// ---------------- host orchestration ------------------------------------------
static void run_layer(const float* x, int din, int dout, int hd,
                      const float* W, const float* a,
                      const float* g, const float* b,
                      const int* src, const int* dst,
                      float* wx, float* ssrc, float* sdst,
                      float* denom, float* eexp, float* out)
{
    const int N = NNODES;
    const int E = NEDGES;

    cudaMemsetAsync(denom, 0, (size_t)N * HEADS * sizeof(float), 0);
    cudaMemsetAsync(out,   0, (size_t)N * dout  * sizeof(float), 0);

    // GEMM: wx = x @ W
    {
        dim3 grid(dout / BN, (N + BM - 1) / BM);
        sgemm_kernel<<<grid, 256>>>(x, W, wx, N, dout, din);
    }
    // scores
    {
        const int warps = N * HEADS;
        const long long threads = (long long)warps * 32;
        scores_kernel<<<(int)((threads + 255) / 256), 256>>>(wx, a, ssrc, sdst, N, hd);
    }
    // edge logits + denom
    edge_attn_kernel<<<(E + 255) / 256, 256>>>(src, dst, ssrc, sdst, eexp, denom, E);
    // aggregation
    {
        const long long total = (long long)E * hd;
        const int blocks = (int)((total + 255) / 256);
        if (hd == 64)
            aggregate_kernel<64><<<blocks, 256>>>(src, dst, eexp, denom, wx, out, E);
        else
            aggregate_kernel<128><<<blocks, 256>>>(src, dst, eexp, denom, wx, out, E);
    }
    // ELU + LayerNorm in-place
    {
        const long long threads = (long long)N * 32;
        const int blocks = (int)((threads + 255) / 256);
        if (dout == 256)
            epilogue_kernel<256><<<blocks, 256>>>(out, g, b, N);
        else
            epilogue_kernel<512><<<blocks, 256>>>(out, g, b, N);
    }
}

extern "C" void kernel_launch(void* const* d_in, const int* in_sizes, int n_in,
                              void* d_out, int out_size)
{
    const float* x0 = (const float*)d_in[0];
    const int*   ei = (const int*)d_in[1];    // edge_index is int32 (JAX x64 disabled)
    const float* W1 = (const float*)d_in[2];
    const float* a1 = (const float*)d_in[3];
    const float* g1 = (const float*)d_in[4];
    const float* b1 = (const float*)d_in[5];
    const float* W2 = (const float*)d_in[6];
    const float* a2 = (const float*)d_in[7];
    const float* g2 = (const float*)d_in[8];
    const float* b2 = (const float*)d_in[9];
    const float* W3 = (const float*)d_in[10];
    const float* a3 = (const float*)d_in[11];
    const float* g3 = (const float*)d_in[12];
    const float* b3 = (const float*)d_in[13];

    const int* src = ei;
    const int* dst = ei + NEDGES;

    float *wx, *bufA, *bufB, *ssrc, *sdst, *denom, *eexp;
    cudaGetSymbolAddress((void**)&wx,    g_Wx);
    cudaGetSymbolAddress((void**)&bufA,  g_bufA);
    cudaGetSymbolAddress((void**)&bufB,  g_bufB);
    cudaGetSymbolAddress((void**)&ssrc,  g_ssrc);
    cudaGetSymbolAddress((void**)&sdst,  g_sdst);
    cudaGetSymbolAddress((void**)&denom, g_denom);
    cudaGetSymbolAddress((void**)&eexp,  g_eexp);

    float* outf = (float*)d_out;

    // layer 1: 523 -> 256 (hd 64)
    run_layer(x0,   523, 256,  64, W1, a1, g1, b1, src, dst, wx, ssrc, sdst, denom, eexp, bufA);
    // layer 2: 256 -> 256 (hd 64)
    run_layer(bufA, 256, 256,  64, W2, a2, g2, b2, src, dst, wx, ssrc, sdst, denom, eexp, bufB);
    // layer 3: 256 -> 512 (hd 128), final output straight into d_out
    run_layer(bufB, 256, 512, 128, W3, a3, g3, b3, src, dst, wx, ssrc, sdst, denom, eexp, outf);
}

// round 3
// speedup vs baseline: 1.5824x; 1.5824x over previous
#include <cuda_runtime.h>
#include <math.h>

#define NNODES 50000
#define NEDGES 400000
#define HEADS  4

// ---------------- scratch (device globals; no allocation allowed) -------------
__device__ float g_Wx  [NNODES * 512];   // Wx for current layer (max dout=512)
__device__ float g_bufA[NNODES * 256];   // layer-1 output / layer-2 input
__device__ float g_bufB[NNODES * 256];   // layer-2 output / layer-3 input
__device__ float g_ssrc[NNODES * HEADS];
__device__ float g_sdst[NNODES * HEADS];
// CSR (built once per launch; edge_index identical for all 3 layers)
__device__ int g_cnt   [NNODES];
__device__ int g_rowptr[NNODES + 1];
__device__ int g_fill  [NNODES];
__device__ int g_srcs  [NEDGES];        // src node ids grouped by dst

// ---------------- SGEMM: C[M,N] = A[M,K] @ B[K,N] ----------------------------
#define BM 128
#define BN 128
#define BK 8
#define TM 8
#define TN 8

__global__ __launch_bounds__(256, 2)
void sgemm_kernel(const float* __restrict__ A, const float* __restrict__ B,
                  float* __restrict__ C, int M, int N, int K)
{
    __shared__ float As[BK][BM];
    __shared__ float Bs[BK][BN];

    const int tid = threadIdx.x;
    const int block_row = blockIdx.y * BM;
    const int block_col = blockIdx.x * BN;

    const int tx = tid % 16;
    const int ty = tid / 16;

    const int a_row = tid >> 1;
    const int a_col = (tid & 1) * 4;
    const int b_row = tid >> 5;
    const int b_col = (tid & 31) * 4;

    float acc[TM][TN];
#pragma unroll
    for (int i = 0; i < TM; i++)
#pragma unroll
        for (int j = 0; j < TN; j++) acc[i][j] = 0.0f;

    for (int k0 = 0; k0 < K; k0 += BK) {
        const int gr = block_row + a_row;
#pragma unroll
        for (int i = 0; i < 4; i++) {
            const int gc = k0 + a_col + i;
            float v = 0.0f;
            if (gr < M && gc < K) v = A[(long long)gr * K + gc];
            As[a_col + i][a_row] = v;
        }
        {
            const int gk = k0 + b_row;
            float4 v = make_float4(0.f, 0.f, 0.f, 0.f);
            if (gk < K)
                v = *(const float4*)&B[(long long)gk * N + block_col + b_col];
            Bs[b_row][b_col + 0] = v.x;
            Bs[b_row][b_col + 1] = v.y;
            Bs[b_row][b_col + 2] = v.z;
            Bs[b_row][b_col + 3] = v.w;
        }
        __syncthreads();

#pragma unroll
        for (int k = 0; k < BK; k++) {
            float ar[TM], br[TN];
            *(float4*)&ar[0] = *(const float4*)&As[k][ty * TM + 0];
            *(float4*)&ar[4] = *(const float4*)&As[k][ty * TM + 4];
            *(float4*)&br[0] = *(const float4*)&Bs[k][tx * TN + 0];
            *(float4*)&br[4] = *(const float4*)&Bs[k][tx * TN + 4];
#pragma unroll
            for (int i = 0; i < TM; i++)
#pragma unroll
                for (int j = 0; j < TN; j++)
                    acc[i][j] = fmaf(ar[i], br[j], acc[i][j]);
        }
        __syncthreads();
    }

#pragma unroll
    for (int i = 0; i < TM; i++) {
        const int gr = block_row + ty * TM + i;
        if (gr < M) {
            float* c = &C[(long long)gr * N + block_col + tx * TN];
            *(float4*)&c[0] = make_float4(acc[i][0], acc[i][1], acc[i][2], acc[i][3]);
            *(float4*)&c[4] = make_float4(acc[i][4], acc[i][5], acc[i][6], acc[i][7]);
        }
    }
}

// ---------------- CSR construction (dst-grouped) -------------------------------
__global__ void hist_kernel(const int* __restrict__ dst, int* __restrict__ cnt, int E)
{
    const int e = blockIdx.x * blockDim.x + threadIdx.x;
    if (e < E) atomicAdd(&cnt[dst[e]], 1);
}

// single-block scan over N counts -> exclusive rowptr + fill cursors
__global__ void scan_kernel(const int* __restrict__ cnt, int* __restrict__ rowptr,
                            int* __restrict__ fill, int n)
{
    __shared__ int sh[1024];
    __shared__ int carry;
    if (threadIdx.x == 0) { carry = 0; rowptr[0] = 0; }
    __syncthreads();
    for (int base = 0; base < n; base += 1024) {
        const int i = base + (int)threadIdx.x;
        const int v = (i < n) ? cnt[i] : 0;
        sh[threadIdx.x] = v;
        __syncthreads();
#pragma unroll
        for (int o = 1; o < 1024; o <<= 1) {
            int t = (threadIdx.x >= (unsigned)o) ? sh[threadIdx.x - o] : 0;
            __syncthreads();
            sh[threadIdx.x] += t;
            __syncthreads();
        }
        const int incl = sh[threadIdx.x];
        if (i < n) {
            rowptr[i + 1] = carry + incl;
            fill[i] = carry + incl - v;   // exclusive start
        }
        __syncthreads();
        if (threadIdx.x == 0) carry += sh[1023];
        __syncthreads();
    }
}

__global__ void scatter_kernel(const int* __restrict__ src, const int* __restrict__ dst,
                               int* __restrict__ fill, int* __restrict__ srcs, int E)
{
    const int e = blockIdx.x * blockDim.x + threadIdx.x;
    if (e >= E) return;
    const int pos = atomicAdd(&fill[dst[e]], 1);
    srcs[pos] = src[e];
}

// ---------------- per-(node,head) attention scores ----------------------------
__global__ void scores_kernel(const float* __restrict__ Wx,
                              const float* __restrict__ a,
                              float* __restrict__ s_src, float* __restrict__ s_dst,
                              int n, int hd)
{
    const int warp = (blockIdx.x * blockDim.x + threadIdx.x) >> 5;
    const int lane = threadIdx.x & 31;
    if (warp >= n * HEADS) return;
    const int node = warp / HEADS;
    const int h    = warp % HEADS;
    const float* row = Wx + (long long)node * HEADS * hd + h * hd;
    float ss = 0.f, sd = 0.f;
    for (int d = lane; d < hd; d += 32) {
        const float v = row[d];
        ss = fmaf(v, a[d], ss);
        sd = fmaf(v, a[hd + d], sd);
    }
#pragma unroll
    for (int o = 16; o; o >>= 1) {
        ss += __shfl_xor_sync(0xffffffffu, ss, o);
        sd += __shfl_xor_sync(0xffffffffu, sd, o);
    }
    if (lane == 0) {
        s_src[node * HEADS + h] = ss;
        s_dst[node * HEADS + h] = sd;
    }
}

// ------ fused edge-softmax + weighted aggregation + ELU + LayerNorm -----------
// One warp per destination node. Zero atomics. Output written once, coalesced.
template <int DOUT>
__global__ __launch_bounds__(256)
void gat_aggregate_ln_kernel(const int* __restrict__ rowptr,
                             const int* __restrict__ srcs,
                             const float* __restrict__ ssrc,
                             const float* __restrict__ sdst,
                             const float* __restrict__ Wx,
                             const float* __restrict__ g,
                             const float* __restrict__ b,
                             float* __restrict__ out, int n)
{
    const int warp = (blockIdx.x * blockDim.x + threadIdx.x) >> 5;
    const int lane = threadIdx.x & 31;
    if (warp >= n) return;
    const int node = warp;
    const int begin = rowptr[node];
    const int end   = rowptr[node + 1];

    constexpr int PER = DOUT / 32;     // columns per lane (8 or 16)
    const int h = lane >> 3;           // head owned by this lane's columns

    // dst-side score components (broadcast reads, tiny)
    const float4 sdv = *(const float4*)&sdst[node * 4];
    const float sd_arr0 = sdv.x, sd_arr1 = sdv.y, sd_arr2 = sdv.z, sd_arr3 = sdv.w;

    // ---- pass 1: softmax denominator per head ----
    float d0 = 0.f, d1 = 0.f, d2 = 0.f, d3 = 0.f;
    for (int i = begin + lane; i < end; i += 32) {
        const int s = srcs[i];
        const float4 sv = *(const float4*)&ssrc[s * 4];
        float v;
        v = sv.x + sd_arr0; v = v > 0.f ? v : 0.2f * v; d0 += expf(v);
        v = sv.y + sd_arr1; v = v > 0.f ? v : 0.2f * v; d1 += expf(v);
        v = sv.z + sd_arr2; v = v > 0.f ? v : 0.2f * v; d2 += expf(v);
        v = sv.w + sd_arr3; v = v > 0.f ? v : 0.2f * v; d3 += expf(v);
    }
#pragma unroll
    for (int o = 16; o; o >>= 1) {
        d0 += __shfl_xor_sync(0xffffffffu, d0, o);
        d1 += __shfl_xor_sync(0xffffffffu, d1, o);
        d2 += __shfl_xor_sync(0xffffffffu, d2, o);
        d3 += __shfl_xor_sync(0xffffffffu, d3, o);
    }
    const float dh  = (h == 0) ? d0 : (h == 1) ? d1 : (h == 2) ? d2 : d3;
    const float sdh = (h == 0) ? sd_arr0 : (h == 1) ? sd_arr1 : (h == 2) ? sd_arr2 : sd_arr3;
    const float invd = 1.0f / (dh + 1e-8f);

    // ---- pass 2: acc = sum alpha * Wx[src] over incoming edges ----
    float acc[PER];
#pragma unroll
    for (int j = 0; j < PER; j++) acc[j] = 0.f;

    const int colbase = lane * PER;
    for (int i = begin; i < end; i++) {
        const int s = srcs[i];                       // warp-uniform load
        float e = ssrc[s * 4 + h] + sdh;
        e = e > 0.f ? e : 0.2f * e;
        const float alpha = expf(e) * invd;
        const float4* w = (const float4*)&Wx[(long long)s * DOUT + colbase];
#pragma unroll
        for (int j = 0; j < PER / 4; j++) {
            const float4 wv = w[j];
            acc[j * 4 + 0] = fmaf(alpha, wv.x, acc[j * 4 + 0]);
            acc[j * 4 + 1] = fmaf(alpha, wv.y, acc[j * 4 + 1]);
            acc[j * 4 + 2] = fmaf(alpha, wv.z, acc[j * 4 + 2]);
            acc[j * 4 + 3] = fmaf(alpha, wv.w, acc[j * 4 + 3]);
        }
    }

    // ---- ELU + LayerNorm ----
    float sum = 0.f, sumsq = 0.f;
#pragma unroll
    for (int j = 0; j < PER; j++) {
        float v = acc[j];
        v = (v > 0.f) ? v : expm1f(v);
        acc[j] = v;
        sum += v;
        sumsq = fmaf(v, v, sumsq);
    }
#pragma unroll
    for (int o = 16; o; o >>= 1) {
        sum   += __shfl_xor_sync(0xffffffffu, sum, o);
        sumsq += __shfl_xor_sync(0xffffffffu, sumsq, o);
    }
    const float inv = 1.0f / (float)DOUT;
    const float mu  = sum * inv;
    const float var = sumsq * inv - mu * mu;
    const float rs  = rsqrtf(var + 1e-5f);

    float* orow = &out[(long long)node * DOUT + colbase];
#pragma unroll
    for (int j = 0; j < PER / 4; j++) {
        const float4 gv = *(const float4*)&g[colbase + j * 4];
        const float4 bv = *(const float4*)&b[colbase + j * 4];
        float4 ov;
        ov.x = (acc[j * 4 + 0] - mu) * rs * gv.x + bv.x;
        ov.y = (acc[j * 4 + 1] - mu) * rs * gv.y + bv.y;
        ov.z = (acc[j * 4 + 2] - mu) * rs * gv.z + bv.z;
        ov.w = (acc[j * 4 + 3] - mu) * rs * gv.w + bv.w;
        *(float4*)&orow[j * 4] = ov;
    }
}

// ---------------- host orchestration ------------------------------------------
static void run_layer(const float* x, int din, int dout, int hd,
                      const float* W, const float* a,
                      const float* g, const float* b,
                      const int* rowptr, const int* srcs,
                      float* wx, float* ssrc, float* sdst, float* out)
{
    const int N = NNODES;

    // GEMM: wx = x @ W
    {
        dim3 grid(dout / BN, (N + BM - 1) / BM);
        sgemm_kernel<<<grid, 256>>>(x, W, wx, N, dout, din);
    }
    // scores
    {
        const long long threads = (long long)N * HEADS * 32;
        scores_kernel<<<(int)((threads + 255) / 256), 256>>>(wx, a, ssrc, sdst, N, hd);
    }
    // fused softmax + aggregate + ELU + LN
    {
        const long long threads = (long long)N * 32;
        const int blocks = (int)((threads + 255) / 256);
        if (dout == 256)
            gat_aggregate_ln_kernel<256><<<blocks, 256>>>(rowptr, srcs, ssrc, sdst, wx, g, b, out, N);
        else
            gat_aggregate_ln_kernel<512><<<blocks, 256>>>(rowptr, srcs, ssrc, sdst, wx, g, b, out, N);
    }
}

extern "C" void kernel_launch(void* const* d_in, const int* in_sizes, int n_in,
                              void* d_out, int out_size)
{
    const float* x0 = (const float*)d_in[0];
    const int*   ei = (const int*)d_in[1];    // edge_index is int32
    const float* W1 = (const float*)d_in[2];
    const float* a1 = (const float*)d_in[3];
    const float* g1 = (const float*)d_in[4];
    const float* b1 = (const float*)d_in[5];
    const float* W2 = (const float*)d_in[6];
    const float* a2 = (const float*)d_in[7];
    const float* g2 = (const float*)d_in[8];
    const float* b2 = (const float*)d_in[9];
    const float* W3 = (const float*)d_in[10];
    const float* a3 = (const float*)d_in[11];
    const float* g3 = (const float*)d_in[12];
    const float* b3 = (const float*)d_in[13];

    const int* src = ei;
    const int* dst = ei + NEDGES;

    float *wx, *bufA, *bufB, *ssrc, *sdst;
    int *cnt, *rowptr, *fill, *srcs;
    cudaGetSymbolAddress((void**)&wx,     g_Wx);
    cudaGetSymbolAddress((void**)&bufA,   g_bufA);
    cudaGetSymbolAddress((void**)&bufB,   g_bufB);
    cudaGetSymbolAddress((void**)&ssrc,   g_ssrc);
    cudaGetSymbolAddress((void**)&sdst,   g_sdst);
    cudaGetSymbolAddress((void**)&cnt,    g_cnt);
    cudaGetSymbolAddress((void**)&rowptr, g_rowptr);
    cudaGetSymbolAddress((void**)&fill,   g_fill);
    cudaGetSymbolAddress((void**)&srcs,   g_srcs);

    // ---- build dst-CSR once; reused by all 3 layers ----
    cudaMemsetAsync(cnt, 0, NNODES * sizeof(int), 0);
    hist_kernel<<<(NEDGES + 255) / 256, 256>>>(dst, cnt, NEDGES);
    scan_kernel<<<1, 1024>>>(cnt, rowptr, fill, NNODES);
    scatter_kernel<<<(NEDGES + 255) / 256, 256>>>(src, dst, fill, srcs, NEDGES);

    float* outf = (float*)d_out;

    // layer 1: 523 -> 256 (hd 64)
    run_layer(x0,   523, 256,  64, W1, a1, g1, b1, rowptr, srcs, wx, ssrc, sdst, bufA);
    // layer 2: 256 -> 256 (hd 64)
    run_layer(bufA, 256, 256,  64, W2, a2, g2, b2, rowptr, srcs, wx, ssrc, sdst, bufB);
    // layer 3: 256 -> 512 (hd 128), final output straight into d_out
    run_layer(bufB, 256, 512, 128, W3, a3, g3, b3, rowptr, srcs, wx, ssrc, sdst, outf);
}

// round 4
// speedup vs baseline: 1.7350x; 1.0964x over previous
#include <cuda_runtime.h>
#include <math.h>

#define NNODES 50000
#define NEDGES 400000
#define HEADS  4

typedef unsigned long long ull;

// ---------------- scratch (device globals; no allocation allowed) -------------
__device__ float g_Wx  [NNODES * 512];
__device__ float g_bufA[NNODES * 256];
__device__ float g_bufB[NNODES * 256];
__device__ float g_ssrc[NNODES * HEADS];
__device__ float g_sdst[NNODES * HEADS];
__device__ int g_cnt   [NNODES];
__device__ int g_rowptr[NNODES + 1];
__device__ int g_fill  [NNODES];
__device__ int g_srcs  [NEDGES];

// ---------------- SGEMM with packed f32x2 FMA (FFMA2) -------------------------
// C[M,N] = A[M,K] @ B[K,N]; N % 128 == 0. 128x128 tile, BK=8, 256 thr, 8x8 micro.
#define BM 128
#define BN 128
#define BK 8
#define TM 8
#define TN 8

__device__ __forceinline__ ull pack_dup(float x) {
    ull r;
    asm("mov.b64 %0, {%1, %1};" : "=l"(r) : "f"(x));
    return r;
}
__device__ __forceinline__ void ffma2(ull& d, ull a, ull b) {
    asm("fma.rn.f32x2 %0, %1, %2, %0;" : "+l"(d) : "l"(a), "l"(b));
}

__global__ __launch_bounds__(256, 2)
void sgemm_kernel(const float* __restrict__ A, const float* __restrict__ B,
                  float* __restrict__ C, int M, int N, int K)
{
    __shared__ float As[2][BK][BM];
    __shared__ float Bs[2][BK][BN];

    const int tid = threadIdx.x;
    const int block_row = blockIdx.y * BM;
    const int block_col = blockIdx.x * BN;

    const int tx = tid % 16;           // col group (8 cols each)
    const int ty = tid / 16;           // row group (8 rows each)

    const int a_row = tid >> 1;        // 0..127
    const int a_col = (tid & 1) * 4;   // 0 or 4
    const int b_row = tid >> 5;        // 0..7
    const int b_col = (tid & 31) * 4;  // 0..124

    const int gr_a = block_row + a_row;

    // packed accumulators: acc2[i][jp] holds cols (tx*8 + 2*jp, +1) for row ty*8+i
    ull acc2[TM][TN / 2];
#pragma unroll
    for (int i = 0; i < TM; i++)
#pragma unroll
        for (int j = 0; j < TN / 2; j++) acc2[i][j] = 0ull;

    // ---- preload tile 0 into buffer 0 ----
    {
#pragma unroll
        for (int i = 0; i < 4; i++) {
            const int gc = a_col + i;
            float v = 0.0f;
            if (gr_a < M && gc < K) v = A[(long long)gr_a * K + gc];
            As[0][a_col + i][a_row] = v;
        }
        float4 v = make_float4(0.f, 0.f, 0.f, 0.f);
        if (b_row < K)
            v = *(const float4*)&B[(long long)b_row * N + block_col + b_col];
        Bs[0][b_row][b_col + 0] = v.x;
        Bs[0][b_row][b_col + 1] = v.y;
        Bs[0][b_row][b_col + 2] = v.z;
        Bs[0][b_row][b_col + 3] = v.w;
    }
    __syncthreads();

    int buf = 0;
    for (int k0 = 0; k0 < K; k0 += BK) {
        const int kn = k0 + BK;
        const bool more = kn < K;

        // prefetch next tile into registers (issued early, consumed after compute)
        float pa[4];
        float4 pb = make_float4(0.f, 0.f, 0.f, 0.f);
        if (more) {
#pragma unroll
            for (int i = 0; i < 4; i++) {
                const int gc = kn + a_col + i;
                pa[i] = 0.0f;
                if (gr_a < M && gc < K) pa[i] = A[(long long)gr_a * K + gc];
            }
            const int gk = kn + b_row;
            if (gk < K)
                pb = *(const float4*)&B[(long long)gk * N + block_col + b_col];
        }

        // compute on current buffer
#pragma unroll
        for (int k = 0; k < BK; k++) {
            float ar[TM];
            *(float4*)&ar[0] = *(const float4*)&As[buf][k][ty * TM + 0];
            *(float4*)&ar[4] = *(const float4*)&As[buf][k][ty * TM + 4];
            const ulonglong2 bA = *(const ulonglong2*)&Bs[buf][k][tx * TN + 0];
            const ulonglong2 bB = *(const ulonglong2*)&Bs[buf][k][tx * TN + 4];
            ull b2[4];
            b2[0] = bA.x; b2[1] = bA.y; b2[2] = bB.x; b2[3] = bB.y;
#pragma unroll
            for (int i = 0; i < TM; i++) {
                const ull a2 = pack_dup(ar[i]);
#pragma unroll
                for (int j = 0; j < TN / 2; j++)
                    ffma2(acc2[i][j], a2, b2[j]);
            }
        }

        // stage prefetched tile into the other buffer
        if (more) {
#pragma unroll
            for (int i = 0; i < 4; i++)
                As[buf ^ 1][a_col + i][a_row] = pa[i];
            Bs[buf ^ 1][b_row][b_col + 0] = pb.x;
            Bs[buf ^ 1][b_row][b_col + 1] = pb.y;
            Bs[buf ^ 1][b_row][b_col + 2] = pb.z;
            Bs[buf ^ 1][b_row][b_col + 3] = pb.w;
        }
        __syncthreads();
        buf ^= 1;
    }

    // store (unpack pairs; cols tx*8..tx*8+7 contiguous)
#pragma unroll
    for (int i = 0; i < TM; i++) {
        const int gr = block_row + ty * TM + i;
        if (gr < M) {
            float out[TN];
#pragma unroll
            for (int j = 0; j < TN / 2; j++) {
                const float2 f = *(const float2*)&acc2[i][j];
                out[2 * j]     = f.x;
                out[2 * j + 1] = f.y;
            }
            float* c = &C[(long long)gr * N + block_col + tx * TN];
            *(float4*)&c[0] = make_float4(out[0], out[1], out[2], out[3]);
            *(float4*)&c[4] = make_float4(out[4], out[5], out[6], out[7]);
        }
    }
}

// ---------------- CSR construction (dst-grouped) -------------------------------
__global__ void hist_kernel(const int* __restrict__ dst, int* __restrict__ cnt, int E)
{
    const int e = blockIdx.x * blockDim.x + threadIdx.x;
    if (e < E) atomicAdd(&cnt[dst[e]], 1);
}

__global__ void scan_kernel(const int* __restrict__ cnt, int* __restrict__ rowptr,
                            int* __restrict__ fill, int n)
{
    __shared__ int sh[1024];
    __shared__ int carry;
    if (threadIdx.x == 0) { carry = 0; rowptr[0] = 0; }
    __syncthreads();
    for (int base = 0; base < n; base += 1024) {
        const int i = base + (int)threadIdx.x;
        const int v = (i < n) ? cnt[i] : 0;
        sh[threadIdx.x] = v;
        __syncthreads();
#pragma unroll
        for (int o = 1; o < 1024; o <<= 1) {
            int t = (threadIdx.x >= (unsigned)o) ? sh[threadIdx.x - o] : 0;
            __syncthreads();
            sh[threadIdx.x] += t;
            __syncthreads();
        }
        const int incl = sh[threadIdx.x];
        if (i < n) {
            rowptr[i + 1] = carry + incl;
            fill[i] = carry + incl - v;
        }
        __syncthreads();
        if (threadIdx.x == 0) carry += sh[1023];
        __syncthreads();
    }
}

__global__ void scatter_kernel(const int* __restrict__ src, const int* __restrict__ dst,
                               int* __restrict__ fill, int* __restrict__ srcs, int E)
{
    const int e = blockIdx.x * blockDim.x + threadIdx.x;
    if (e >= E) return;
    const int pos = atomicAdd(&fill[dst[e]], 1);
    srcs[pos] = src[e];
}

// ---------------- per-(node,head) attention scores ----------------------------
__global__ void scores_kernel(const float* __restrict__ Wx,
                              const float* __restrict__ a,
                              float* __restrict__ s_src, float* __restrict__ s_dst,
                              int n, int hd)
{
    const int warp = (blockIdx.x * blockDim.x + threadIdx.x) >> 5;
    const int lane = threadIdx.x & 31;
    if (warp >= n * HEADS) return;
    const int node = warp / HEADS;
    const int h    = warp % HEADS;
    const float* row = Wx + (long long)node * HEADS * hd + h * hd;
    float ss = 0.f, sd = 0.f;
    for (int d = lane; d < hd; d += 32) {
        const float v = row[d];
        ss = fmaf(v, a[d], ss);
        sd = fmaf(v, a[hd + d], sd);
    }
#pragma unroll
    for (int o = 16; o; o >>= 1) {
        ss += __shfl_xor_sync(0xffffffffu, ss, o);
        sd += __shfl_xor_sync(0xffffffffu, sd, o);
    }
    if (lane == 0) {
        s_src[node * HEADS + h] = ss;
        s_dst[node * HEADS + h] = sd;
    }
}

// ------ fused edge-softmax + weighted aggregation + ELU + LayerNorm -----------
template <int DOUT>
__global__ __launch_bounds__(256)
void gat_aggregate_ln_kernel(const int* __restrict__ rowptr,
                             const int* __restrict__ srcs,
                             const float* __restrict__ ssrc,
                             const float* __restrict__ sdst,
                             const float* __restrict__ Wx,
                             const float* __restrict__ g,
                             const float* __restrict__ b,
                             float* __restrict__ out, int n)
{
    const int warp = (blockIdx.x * blockDim.x + threadIdx.x) >> 5;
    const int lane = threadIdx.x & 31;
    if (warp >= n) return;
    const int node = warp;
    const int begin = rowptr[node];
    const int end   = rowptr[node + 1];

    constexpr int PER = DOUT / 32;
    const int h = lane >> 3;

    const float4 sdv = *(const float4*)&sdst[node * 4];
    const float sd0 = sdv.x, sd1 = sdv.y, sd2 = sdv.z, sd3 = sdv.w;

    // pass 1: softmax denominator per head
    float d0 = 0.f, d1 = 0.f, d2 = 0.f, d3 = 0.f;
    for (int i = begin + lane; i < end; i += 32) {
        const int s = srcs[i];
        const float4 sv = *(const float4*)&ssrc[s * 4];
        float v;
        v = sv.x + sd0; v = v > 0.f ? v : 0.2f * v; d0 += expf(v);
        v = sv.y + sd1; v = v > 0.f ? v : 0.2f * v; d1 += expf(v);
        v = sv.z + sd2; v = v > 0.f ? v : 0.2f * v; d2 += expf(v);
        v = sv.w + sd3; v = v > 0.f ? v : 0.2f * v; d3 += expf(v);
    }
#pragma unroll
    for (int o = 16; o; o >>= 1) {
        d0 += __shfl_xor_sync(0xffffffffu, d0, o);
        d1 += __shfl_xor_sync(0xffffffffu, d1, o);
        d2 += __shfl_xor_sync(0xffffffffu, d2, o);
        d3 += __shfl_xor_sync(0xffffffffu, d3, o);
    }
    const float dh  = (h == 0) ? d0 : (h == 1) ? d1 : (h == 2) ? d2 : d3;
    const float sdh = (h == 0) ? sd0 : (h == 1) ? sd1 : (h == 2) ? sd2 : sd3;
    const float invd = 1.0f / (dh + 1e-8f);

    // pass 2: acc = sum alpha * Wx[src]
    float acc[PER];
#pragma unroll
    for (int j = 0; j < PER; j++) acc[j] = 0.f;

    const int colbase = lane * PER;
    for (int i = begin; i < end; i++) {
        const int s = srcs[i];
        float e = ssrc[s * 4 + h] + sdh;
        e = e > 0.f ? e : 0.2f * e;
        const float alpha = expf(e) * invd;
        const float4* w = (const float4*)&Wx[(long long)s * DOUT + colbase];
#pragma unroll
        for (int j = 0; j < PER / 4; j++) {
            const float4 wv = w[j];
            acc[j * 4 + 0] = fmaf(alpha, wv.x, acc[j * 4 + 0]);
            acc[j * 4 + 1] = fmaf(alpha, wv.y, acc[j * 4 + 1]);
            acc[j * 4 + 2] = fmaf(alpha, wv.z, acc[j * 4 + 2]);
            acc[j * 4 + 3] = fmaf(alpha, wv.w, acc[j * 4 + 3]);
        }
    }

    // ELU + LayerNorm
    float sum = 0.f, sumsq = 0.f;
#pragma unroll
    for (int j = 0; j < PER; j++) {
        float v = acc[j];
        v = (v > 0.f) ? v : expm1f(v);
        acc[j] = v;
        sum += v;
        sumsq = fmaf(v, v, sumsq);
    }
#pragma unroll
    for (int o = 16; o; o >>= 1) {
        sum   += __shfl_xor_sync(0xffffffffu, sum, o);
        sumsq += __shfl_xor_sync(0xffffffffu, sumsq, o);
    }
    const float inv = 1.0f / (float)DOUT;
    const float mu  = sum * inv;
    const float var = sumsq * inv - mu * mu;
    const float rs  = rsqrtf(var + 1e-5f);

    float* orow = &out[(long long)node * DOUT + colbase];
#pragma unroll
    for (int j = 0; j < PER / 4; j++) {
        const float4 gv = *(const float4*)&g[colbase + j * 4];
        const float4 bv = *(const float4*)&b[colbase + j * 4];
        float4 ov;
        ov.x = (acc[j * 4 + 0] - mu) * rs * gv.x + bv.x;
        ov.y = (acc[j * 4 + 1] - mu) * rs * gv.y + bv.y;
        ov.z = (acc[j * 4 + 2] - mu) * rs * gv.z + bv.z;
        ov.w = (acc[j * 4 + 3] - mu) * rs * gv.w + bv.w;
        *(float4*)&orow[j * 4] = ov;
    }
}

// ---------------- host orchestration ------------------------------------------
static void run_layer(const float* x, int din, int dout, int hd,
                      const float* W, const float* a,
                      const float* g, const float* b,
                      const int* rowptr, const int* srcs,
                      float* wx, float* ssrc, float* sdst, float* out)
{
    const int N = NNODES;

    {
        dim3 grid(dout / BN, (N + BM - 1) / BM);
        sgemm_kernel<<<grid, 256>>>(x, W, wx, N, dout, din);
    }
    {
        const long long threads = (long long)N * HEADS * 32;
        scores_kernel<<<(int)((threads + 255) / 256), 256>>>(wx, a, ssrc, sdst, N, hd);
    }
    {
        const long long threads = (long long)N * 32;
        const int blocks = (int)((threads + 255) / 256);
        if (dout == 256)
            gat_aggregate_ln_kernel<256><<<blocks, 256>>>(rowptr, srcs, ssrc, sdst, wx, g, b, out, N);
        else
            gat_aggregate_ln_kernel<512><<<blocks, 256>>>(rowptr, srcs, ssrc, sdst, wx, g, b, out, N);
    }
}

extern "C" void kernel_launch(void* const* d_in, const int* in_sizes, int n_in,
                              void* d_out, int out_size)
{
    const float* x0 = (const float*)d_in[0];
    const int*   ei = (const int*)d_in[1];
    const float* W1 = (const float*)d_in[2];
    const float* a1 = (const float*)d_in[3];
    const float* g1 = (const float*)d_in[4];
    const float* b1 = (const float*)d_in[5];
    const float* W2 = (const float*)d_in[6];
    const float* a2 = (const float*)d_in[7];
    const float* g2 = (const float*)d_in[8];
    const float* b2 = (const float*)d_in[9];
    const float* W3 = (const float*)d_in[10];
    const float* a3 = (const float*)d_in[11];
    const float* g3 = (const float*)d_in[12];
    const float* b3 = (const float*)d_in[13];

    const int* src = ei;
    const int* dst = ei + NEDGES;

    float *wx, *bufA, *bufB, *ssrc, *sdst;
    int *cnt, *rowptr, *fill, *srcs;
    cudaGetSymbolAddress((void**)&wx,     g_Wx);
    cudaGetSymbolAddress((void**)&bufA,   g_bufA);
    cudaGetSymbolAddress((void**)&bufB,   g_bufB);
    cudaGetSymbolAddress((void**)&ssrc,   g_ssrc);
    cudaGetSymbolAddress((void**)&sdst,   g_sdst);
    cudaGetSymbolAddress((void**)&cnt,    g_cnt);
    cudaGetSymbolAddress((void**)&rowptr, g_rowptr);
    cudaGetSymbolAddress((void**)&fill,   g_fill);
    cudaGetSymbolAddress((void**)&srcs,   g_srcs);

    // build dst-CSR once; reused by all 3 layers
    cudaMemsetAsync(cnt, 0, NNODES * sizeof(int), 0);
    hist_kernel<<<(NEDGES + 255) / 256, 256>>>(dst, cnt, NEDGES);
    scan_kernel<<<1, 1024>>>(cnt, rowptr, fill, NNODES);
    scatter_kernel<<<(NEDGES + 255) / 256, 256>>>(src, dst, fill, srcs, NEDGES);

    float* outf = (float*)d_out;

    run_layer(x0,   523, 256,  64, W1, a1, g1, b1, rowptr, srcs, wx, ssrc, sdst, bufA);
    run_layer(bufA, 256, 256,  64, W2, a2, g2, b2, rowptr, srcs, wx, ssrc, sdst, bufB);
    run_layer(bufB, 256, 512, 128, W3, a3, g3, b3, rowptr, srcs, wx, ssrc, sdst, outf);
}